// round 2
// baseline (speedup 1.0000x reference)
#include <cuda_runtime.h>
#include <math.h>

#define BATCH 32
#define H 1024
#define W 1024
#define WR 513
#define NPIX (WR * H)
#define TP 56

__device__ float2 g_bufA[(size_t)BATCH * H * WR];
__device__ float2 g_bufB[(size_t)BATCH * WR * H];
__device__ float2 g_tw[512];
__device__ float  g_coeff[BATCH * TP];
__device__ double g_stats[BATCH * 4];
__device__ int    g_magmax[BATCH];
__device__ int    g_maskcnt;

__global__ void init_kernel() {
    int t = threadIdx.x;
    float s, c;
    sincospif(-(float)t / 512.0f, &s, &c);
    g_tw[t] = make_float2(c, s);
    for (int i = t; i < BATCH * TP; i += 512) g_coeff[i] = 0.0f;
    if (t < BATCH * 4) g_stats[t] = 0.0;
    if (t < BATCH)     g_magmax[t] = 0;
    if (t == 0)        g_maskcnt = 0;
}

__device__ __forceinline__ float2* fft1024(float2* sA, float2* sB, int tid) {
    float2* src = sA;
    float2* dst = sB;
#pragma unroll
    for (int s = 0; s < 10; ++s) {
        const int Ns = 1 << s;
#pragma unroll
        for (int it = 0; it < 2; ++it) {
            int j  = tid + it * 256;
            int jm = j & (Ns - 1);
            float2 u = src[j];
            float2 v = src[j + 512];
            float2 w = g_tw[jm << (9 - s)];
            float vr = v.x * w.x - v.y * w.y;
            float vi = v.x * w.y + v.y * w.x;
            int idx = ((j >> s) << (s + 1)) | jm;
            dst[idx]      = make_float2(u.x + vr, u.y + vi);
            dst[idx + Ns] = make_float2(u.x - vr, u.y - vi);
        }
        float2* tmp = src; src = dst; dst = tmp;
        __syncthreads();
    }
    return src;
}

__global__ void __launch_bounds__(256) row_fft_kernel(const float* __restrict__ x) {
    __shared__ float2 sA[1024];
    __shared__ float2 sB[1024];
    int blk = blockIdx.x;
    int tid = threadIdx.x;
    const float* row = x + (size_t)blk * W;
#pragma unroll
    for (int i = 0; i < 4; ++i) {
        int idx = tid + i * 256;
        sA[idx] = make_float2(row[idx], 0.0f);
    }
    __syncthreads();
    float2* res = fft1024(sA, sB, tid);
    float2* out = g_bufA + (size_t)blk * WR;
    for (int c = tid; c < WR; c += 256) out[c] = res[c];
}

__global__ void transpose_kernel() {
    __shared__ float2 tile[32][33];
    int b  = blockIdx.z;
    int c0 = blockIdx.x * 32;
    int r0 = blockIdx.y * 32;
    int tx = threadIdx.x, ty = threadIdx.y;
    const float2* A = g_bufA + (size_t)b * H * WR;
    float2*       B = g_bufB + (size_t)b * WR * H;
#pragma unroll
    for (int i = ty; i < 32; i += 8) {
        int r = r0 + i, c = c0 + tx;
        if (c < WR) tile[i][tx] = A[(size_t)r * WR + c];
    }
    __syncthreads();
#pragma unroll
    for (int i = ty; i < 32; i += 8) {
        int c = c0 + i, r = r0 + tx;
        if (c < WR) B[(size_t)c * H + r] = tile[tx][i];
    }
}

__global__ void __launch_bounds__(256) col_fft_kernel() {
    __shared__ float2 sA[1024];
    __shared__ float2 sB[1024];
    __shared__ float  sred[8];
    int blk = blockIdx.x;
    int tid = threadIdx.x;
    const float2* in = g_bufB + (size_t)blk * H;
#pragma unroll
    for (int i = 0; i < 4; ++i) {
        int idx = tid + i * 256;
        sA[idx] = in[idx];
    }
    __syncthreads();
    float2* res = fft1024(sA, sB, tid);

    float* pu = (float*)g_bufA;
    float maxm2 = 0.0f;
#pragma unroll
    for (int i = 0; i < 4; ++i) {
        int k = tid + i * 256;
        float2 z = res[k];
        float m2 = fmaf(z.x, z.x, z.y * z.y);
        maxm2 = fmaxf(maxm2, m2);
        float ph = atan2f(z.y, z.x);
        if (ph < 0.0f) ph += 6.28318530717958647692f;
        pu[(size_t)blk * H + k] = ph;
    }
#pragma unroll
    for (int o = 16; o; o >>= 1) maxm2 = fmaxf(maxm2, __shfl_xor_sync(0xffffffffu, maxm2, o));
    if ((tid & 31) == 0) sred[tid >> 5] = maxm2;
    __syncthreads();
    if (tid < 8) {
        maxm2 = sred[tid];
#pragma unroll
        for (int o = 4; o; o >>= 1) maxm2 = fmaxf(maxm2, __shfl_xor_sync(0xffu, maxm2, o));
        if (tid == 0)
            atomicMax(&g_magmax[blk / WR], __float_as_int(sqrtf(maxm2)));
    }
}

__global__ void __launch_bounds__(256) zprep_kernel() {
    int pix = blockIdx.x * 256 + threadIdx.x;
    int c = pix >> 10;
    int r = pix & 1023;
    float xg = (float)c * (1.0f / 256.0f) - 1.0f;
    float yg = (float)r * (2.0f / 1023.0f) - 1.0f;
    float rr = xg * xg + yg * yg;
    float rho = sqrtf(rr);
    float mk = (rho <= 1.0f) ? 1.0f : 0.0f;
    float inv = 1.0f / rho;
    float c1 = xg * inv, s1 = yg * inv;

    float q1 = rho, q2 = q1 * q1;
    float q3 = q2 * q1, q4 = q2 * q2, q5 = q3 * q2, q6 = q3 * q3;
    float q7 = q4 * q3, q8 = q4 * q4, q9 = q5 * q4;

    float c2 = c1 * c1 - s1 * s1, s2 = 2.0f * s1 * c1;
    float c3 = c1 * c2 - s1 * s2, s3 = s1 * c2 + c1 * s2;
    float c4 = c1 * c3 - s1 * s3, s4 = s1 * c3 + c1 * s3;
    float c5 = c1 * c4 - s1 * s4, s5 = s1 * c4 + c1 * s4;
    float c6 = c1 * c5 - s1 * s5, s6 = s1 * c5 + c1 * s5;
    float c7 = c1 * c6 - s1 * s6, s7 = s1 * c6 + c1 * s6;
    float c8 = c1 * c7 - s1 * s7, s8 = s1 * c7 + c1 * s7;
    float c9 = c1 * c8 - s1 * s8, s9 = s1 * c8 + c1 * s8;

    float* Z = (float*)g_bufB;
    size_t p = (size_t)pix;
#define ZST(t, val) Z[(size_t)(t) * NPIX + p] = (val) * mk
    ZST(0, 1.0f);
    ZST(1, q1 * s1);
    ZST(2, q1 * c1);
    ZST(3, q2 * s2);
    ZST(4, 2.0f * q2 - 1.0f);
    ZST(5, q2 * c2);
    ZST(6, q3 * s3);
    float R31 = 3.0f * q3 - 2.0f * q1;
    ZST(7, R31 * s1);
    ZST(8, R31 * c1);
    ZST(9, q3 * c3);
    ZST(10, q4 * s4);
    float R42 = 4.0f * q4 - 3.0f * q2;
    ZST(11, R42 * s2);
    ZST(12, 6.0f * q4 - 6.0f * q2 + 1.0f);
    ZST(13, R42 * c2);
    ZST(14, q4 * c4);
    ZST(15, q5 * s5);
    float R53 = 5.0f * q5 - 4.0f * q3;
    ZST(16, R53 * s3);
    float R51 = 10.0f * q5 - 12.0f * q3 + 3.0f * q1;
    ZST(17, R51 * s1);
    ZST(18, R51 * c1);
    ZST(19, R53 * c3);
    ZST(20, q5 * c5);
    ZST(21, q6 * s6);
    float R64 = 6.0f * q6 - 5.0f * q4;
    ZST(22, R64 * s4);
    float R62 = 15.0f * q6 - 20.0f * q4 + 6.0f * q2;
    ZST(23, R62 * s2);
    ZST(24, 20.0f * q6 - 30.0f * q4 + 12.0f * q2 - 1.0f);
    ZST(25, R62 * c2);
    ZST(26, R64 * c4);
    ZST(27, q6 * c6);
    ZST(28, q7 * s7);
    float R75 = 7.0f * q7 - 6.0f * q5;
    ZST(29, R75 * s5);
    float R73 = 21.0f * q7 - 30.0f * q5 + 10.0f * q3;
    ZST(30, R73 * s3);
    float R71 = 35.0f * q7 - 60.0f * q5 + 30.0f * q3 - 4.0f * q1;
    ZST(31, R71 * s1);
    ZST(32, R71 * c1);
    ZST(33, R73 * c3);
    ZST(34, R75 * c5);
    ZST(35, q7 * c7);
    ZST(36, q8 * s8);
    float R86 = 8.0f * q8 - 7.0f * q6;
    ZST(37, R86 * s6);
    float R84 = 28.0f * q8 - 42.0f * q6 + 15.0f * q4;
    ZST(38, R84 * s4);
    float R82 = 56.0f * q8 - 105.0f * q6 + 60.0f * q4 - 10.0f * q2;
    ZST(39, R82 * s2);
    ZST(40, 70.0f * q8 - 140.0f * q6 + 90.0f * q4 - 20.0f * q2 + 1.0f);
    ZST(41, R82 * c2);
    ZST(42, R84 * c4);
    ZST(43, R86 * c6);
    ZST(44, q8 * c8);
    ZST(45, q9 * s9);
    float R97 = 9.0f * q9 - 8.0f * q7;
    ZST(46, R97 * s7);
    float R95 = 36.0f * q9 - 56.0f * q7 + 21.0f * q5;
    ZST(47, R95 * s5);
    float R93 = 84.0f * q9 - 168.0f * q7 + 105.0f * q5 - 20.0f * q3;
    ZST(48, R93 * s3);
    float R91 = 126.0f * q9 - 280.0f * q7 + 210.0f * q5 - 60.0f * q3 + 5.0f * q1;
    ZST(49, R91 * s1);
    ZST(50, R91 * c1);
    ZST(51, R93 * c3);
    ZST(52, R95 * c5);
    ZST(53, R97 * c7);
    ZST(54, q9 * c9);
    Z[(size_t)55 * NPIX + p] = 0.0f;
#undef ZST

    unsigned bal = __ballot_sync(0xffffffffu, mk > 0.5f);
    if ((threadIdx.x & 31) == 0) atomicAdd(&g_maskcnt, __popc(bal));
}

__global__ void __launch_bounds__(256) stats_kernel() {
    int b = blockIdx.y;
    const float* pu = (const float*)g_bufA + (size_t)b * NPIX;
    float sx = 0.0f, sy = 0.0f, sx2 = 0.0f, sy2 = 0.0f;
    for (int pix = blockIdx.x * 256 + threadIdx.x; pix < NPIX; pix += gridDim.x * 256) {
        int r = pix & 1023;
        int c = pix >> 10;
        float pc = pu[pix];
        float gy, gx;
        if (r == 0)          gy = pu[pix + 1] - pc;
        else if (r == 1023)  gy = pc - pu[pix - 1];
        else                 gy = 0.5f * (pu[pix + 1] - pu[pix - 1]);
        if (c == 0)           gx = pu[pix + H] - pc;
        else if (c == WR - 1) gx = pc - pu[pix - H];
        else                  gx = 0.5f * (pu[pix + H] - pu[pix - H]);
        sx += gx; sx2 = fmaf(gx, gx, sx2);
        sy += gy; sy2 = fmaf(gy, gy, sy2);
    }
    __shared__ double sbuf[8];
    double v[4] = {(double)sx, (double)sy, (double)sx2, (double)sy2};
#pragma unroll
    for (int q = 0; q < 4; ++q) {
        double t = v[q];
#pragma unroll
        for (int o = 16; o; o >>= 1) t += __shfl_down_sync(0xffffffffu, t, o);
        if ((threadIdx.x & 31) == 0) sbuf[threadIdx.x >> 5] = t;
        __syncthreads();
        if (threadIdx.x < 8) {
            t = sbuf[threadIdx.x];
#pragma unroll
            for (int o = 4; o; o >>= 1) t += __shfl_down_sync(0xffu, t, o);
            if (threadIdx.x == 0) atomicAdd(&g_stats[b * 4 + q], t);
        }
        __syncthreads();
    }
}

#define KC 64
__global__ void __launch_bounds__(128) gemm_kernel() {
    __shared__ float pm_s[BATCH][KC + 4];
    __shared__ float z_s[TP][KC + 4];
    const float* pu = (const float*)g_bufA;
    const float* Z  = (const float*)g_bufB;
    int tid = threadIdx.x;
    int bg = tid >> 3;
    int tg = tid & 7;
    int b0 = bg * 2, t0 = tg * 7;
    float acc[2][7];
#pragma unroll
    for (int a = 0; a < 2; ++a)
#pragma unroll
        for (int j = 0; j < 7; ++j) acc[a][j] = 0.0f;

    for (int k0 = blockIdx.x * KC; k0 < NPIX; k0 += gridDim.x * KC) {
        __syncthreads();
        {
            int kk = tid & (KC - 1);
            int row0 = tid >> 6;
#pragma unroll
            for (int i = 0; i < 16; ++i) {
                int row = row0 + i * 2;
                pm_s[row][kk] = pu[(size_t)row * NPIX + k0 + kk];
            }
#pragma unroll
            for (int i = 0; i < 28; ++i) {
                int row = row0 + i * 2;
                z_s[row][kk] = Z[(size_t)row * NPIX + k0 + kk];
            }
        }
        __syncthreads();
#pragma unroll 8
        for (int kk = 0; kk < KC; kk += 4) {
            float4 a0 = *(const float4*)&pm_s[b0][kk];
            float4 a1 = *(const float4*)&pm_s[b0 + 1][kk];
#pragma unroll
            for (int j = 0; j < 7; ++j) {
                float4 zz = *(const float4*)&z_s[t0 + j][kk];
                acc[0][j] = fmaf(a0.x, zz.x, fmaf(a0.y, zz.y, fmaf(a0.z, zz.z, fmaf(a0.w, zz.w, acc[0][j]))));
                acc[1][j] = fmaf(a1.x, zz.x, fmaf(a1.y, zz.y, fmaf(a1.z, zz.z, fmaf(a1.w, zz.w, acc[1][j]))));
            }
        }
    }
#pragma unroll
    for (int j = 0; j < 7; ++j) {
        atomicAdd(&g_coeff[(b0)     * TP + t0 + j], acc[0][j]);
        atomicAdd(&g_coeff[(b0 + 1) * TP + t0 + j], acc[1][j]);
    }
}

__global__ void finalize_kernel(float* __restrict__ out) {
    int b = blockIdx.x;
    int j = threadIdx.x;
    if (j < 55) {
        out[b * 60 + j] = g_coeff[b * TP + j] / (float)g_maskcnt;
    } else if (j < 60) {
        double N = (double)NPIX;
        double sx = g_stats[b * 4 + 0], sy = g_stats[b * 4 + 1];
        double sx2 = g_stats[b * 4 + 2], sy2 = g_stats[b * 4 + 3];
        float v;
        if (j == 55)      v = (float)(sx / N);
        else if (j == 56) v = (float)(sy / N);
        else if (j == 57) v = (float)sqrt(fmax(0.0, (sx2 - sx * sx / N) / (N - 1.0)));
        else if (j == 58) v = (float)sqrt(fmax(0.0, (sy2 - sy * sy / N) / (N - 1.0)));
        else              v = __int_as_float(g_magmax[b]);
        out[b * 60 + j] = v;
    }
}

extern "C" void kernel_launch(void* const* d_in, const int* in_sizes, int n_in,
                              void* d_out, int out_size) {
    (void)in_sizes; (void)n_in; (void)out_size;
    const float* x = (const float*)d_in[0];
    float* out = (float*)d_out;

    init_kernel<<<1, 512>>>();
    row_fft_kernel<<<BATCH * H, 256>>>(x);
    transpose_kernel<<<dim3(17, H / 32, BATCH), dim3(32, 8)>>>();
    col_fft_kernel<<<BATCH * WR, 256>>>();
    zprep_kernel<<<NPIX / 256, 256>>>();
    stats_kernel<<<dim3(128, BATCH), 256>>>();
    gemm_kernel<<<296, 128>>>();
    finalize_kernel<<<BATCH, 64>>>(out);
}

// round 3
// speedup vs baseline: 1.5403x; 1.5403x over previous
#include <cuda_runtime.h>
#include <math.h>

#define BATCH 32
#define H 1024
#define W 1024
#define WR 513
#define NPIX (WR * H)
#define TP 56

__device__ float2 g_bufA[(size_t)BATCH * H * WR];
__device__ float2 g_bufB[(size_t)BATCH * WR * H];
__device__ float2 g_tw[512];
__device__ float  g_coeff[BATCH * TP];
__device__ double g_stats[BATCH * 4];
__device__ int    g_magmax[BATCH];
__device__ int    g_maskcnt;

__device__ __forceinline__ float2 cmul(float2 a, float2 b) {
    return make_float2(a.x * b.x - a.y * b.y, a.x * b.y + a.y * b.x);
}

__global__ void init_kernel() {
    int t = threadIdx.x;
    float s, c;
    sincospif(-(float)t / 512.0f, &s, &c);
    g_tw[t] = make_float2(c, s);
    for (int i = t; i < BATCH * TP; i += 512) g_coeff[i] = 0.0f;
    if (t < BATCH * 4) g_stats[t] = 0.0;
    if (t < BATCH)     g_magmax[t] = 0;
    if (t == 0)        g_maskcnt = 0;
}

/* 1024-pt radix-4 Stockham FFT, 256 threads, 5 stages.
   g_tw[t] = exp(-2*pi*i*t/1024). Caller syncs before; result buffer returned. */
__device__ __forceinline__ float2* fft1024_r4(float2* sA, float2* sB, int tid) {
    float2* src = sA;
    float2* dst = sB;
#pragma unroll
    for (int s = 0; s < 5; ++s) {
        const int Ns = 1 << (2 * s);
        int jm = tid & (Ns - 1);
        float2 a0 = src[tid];
        float2 a1 = src[tid + 256];
        float2 a2 = src[tid + 512];
        float2 a3 = src[tid + 768];
        int i1 = jm << (8 - 2 * s);
        float2 w1 = g_tw[i1];
        float2 w2 = g_tw[2 * i1];
        float2 w3 = cmul(w1, w2);
        a1 = cmul(a1, w1);
        a2 = cmul(a2, w2);
        a3 = cmul(a3, w3);
        float2 t0 = make_float2(a0.x + a2.x, a0.y + a2.y);
        float2 t1 = make_float2(a0.x - a2.x, a0.y - a2.y);
        float2 t2 = make_float2(a1.x + a3.x, a1.y + a3.y);
        float2 t3 = make_float2(a1.x - a3.x, a1.y - a3.y);
        int base = ((tid >> (2 * s)) << (2 * s + 2)) | jm;
        dst[base]          = make_float2(t0.x + t2.x, t0.y + t2.y);
        dst[base + Ns]     = make_float2(t1.x + t3.y, t1.y - t3.x);  /* t1 - i*t3 */
        dst[base + 2 * Ns] = make_float2(t0.x - t2.x, t0.y - t2.y);
        dst[base + 3 * Ns] = make_float2(t1.x - t3.y, t1.y + t3.x);  /* t1 + i*t3 */
        float2* tmp = src; src = dst; dst = tmp;
        __syncthreads();
    }
    return src;
}

/* Two real rows packed into one complex FFT, Hermitian unpack. */
__global__ void __launch_bounds__(256) row_fft_kernel(const float* __restrict__ x) {
    __shared__ float2 sA[1024];
    __shared__ float2 sB[1024];
    int blk = blockIdx.x;                 /* pair index: rows 2*blk, 2*blk+1 */
    int tid = threadIdx.x;
    const float* rowA = x + (size_t)(2 * blk) * W;
    const float* rowB = rowA + W;
#pragma unroll
    for (int i = 0; i < 4; ++i) {
        int idx = tid + i * 256;
        sA[idx] = make_float2(rowA[idx], rowB[idx]);
    }
    __syncthreads();
    float2* res = fft1024_r4(sA, sB, tid);
    float2* outA = g_bufA + (size_t)(2 * blk) * WR;
    float2* outB = outA + WR;
    for (int c = tid; c < WR; c += 256) {
        float2 Zc = res[c];
        float2 Zn = res[(1024 - c) & 1023];
        float ar = 0.5f * (Zc.x + Zn.x);
        float ai = 0.5f * (Zc.y - Zn.y);
        float dr = Zc.x - Zn.x;
        float di = Zc.y + Zn.y;
        outA[c] = make_float2(ar, ai);
        outB[c] = make_float2(0.5f * di, -0.5f * dr);
    }
}

__global__ void transpose_kernel() {
    __shared__ float2 tile[32][33];
    int b  = blockIdx.z;
    int c0 = blockIdx.x * 32;
    int r0 = blockIdx.y * 32;
    int tx = threadIdx.x, ty = threadIdx.y;
    const float2* A = g_bufA + (size_t)b * H * WR;
    float2*       B = g_bufB + (size_t)b * WR * H;
#pragma unroll
    for (int i = ty; i < 32; i += 8) {
        int r = r0 + i, c = c0 + tx;
        if (c < WR) tile[i][tx] = A[(size_t)r * WR + c];
    }
    __syncthreads();
#pragma unroll
    for (int i = ty; i < 32; i += 8) {
        int c = c0 + i, r = r0 + tx;
        if (c < WR) B[(size_t)c * H + r] = tile[tx][i];
    }
}

__global__ void __launch_bounds__(256) col_fft_kernel() {
    __shared__ float2 sA[1024];
    __shared__ float2 sB[1024];
    __shared__ float  sred[8];
    int blk = blockIdx.x;
    int tid = threadIdx.x;
    const float2* in = g_bufB + (size_t)blk * H;
#pragma unroll
    for (int i = 0; i < 4; ++i) {
        int idx = tid + i * 256;
        sA[idx] = in[idx];
    }
    __syncthreads();
    float2* res = fft1024_r4(sA, sB, tid);

    float* pu = (float*)g_bufA;
    float maxm2 = 0.0f;
#pragma unroll
    for (int i = 0; i < 4; ++i) {
        int k = tid + i * 256;
        float2 z = res[k];
        float m2 = fmaf(z.x, z.x, z.y * z.y);
        maxm2 = fmaxf(maxm2, m2);
        float ph = atan2f(z.y, z.x);
        if (ph < 0.0f) ph += 6.28318530717958647692f;
        pu[(size_t)blk * H + k] = ph;
    }
#pragma unroll
    for (int o = 16; o; o >>= 1) maxm2 = fmaxf(maxm2, __shfl_xor_sync(0xffffffffu, maxm2, o));
    if ((tid & 31) == 0) sred[tid >> 5] = maxm2;
    __syncthreads();
    if (tid < 8) {
        maxm2 = sred[tid];
#pragma unroll
        for (int o = 4; o; o >>= 1) maxm2 = fmaxf(maxm2, __shfl_xor_sync(0xffu, maxm2, o));
        if (tid == 0)
            atomicMax(&g_magmax[blk / WR], __float_as_int(sqrtf(maxm2)));
    }
}

/* Gradient stats: vectorized float4 along r; torch.gradient edge handling. */
__global__ void __launch_bounds__(256) stats_kernel() {
    int b = blockIdx.y;
    const float*  pu  = (const float*)g_bufA + (size_t)b * NPIX;
    const float4* pu4 = (const float4*)pu;
    float sx = 0.0f, sy = 0.0f, sx2 = 0.0f, sy2 = 0.0f;
    const int NQ = NPIX / 4;
    for (int q = blockIdx.x * 256 + threadIdx.x; q < NQ; q += gridDim.x * 256) {
        int p = q * 4;
        int r = p & 1023;
        int c = p >> 10;
        float4 v = pu4[q];
        float left  = (r == 0)        ? 0.0f : pu[p - 1];
        float right = (r + 4 == 1024) ? 0.0f : pu[p + 4];
        float gy0 = (r == 0)        ? (v.y - v.x) : 0.5f * (v.y - left);
        float gy1 = 0.5f * (v.z - v.x);
        float gy2 = 0.5f * (v.w - v.y);
        float gy3 = (r + 4 == 1024) ? (v.w - v.z) : 0.5f * (right - v.z);
        float4 up = (c == 0)      ? v : pu4[q - 256];
        float4 dn = (c == WR - 1) ? v : pu4[q + 256];
        float f = (c == 0 || c == WR - 1) ? 1.0f : 0.5f;
        float gx0 = f * (dn.x - up.x);
        float gx1 = f * (dn.y - up.y);
        float gx2 = f * (dn.z - up.z);
        float gx3 = f * (dn.w - up.w);
        sx += gx0 + gx1 + gx2 + gx3;
        sy += gy0 + gy1 + gy2 + gy3;
        sx2 = fmaf(gx0, gx0, fmaf(gx1, gx1, fmaf(gx2, gx2, fmaf(gx3, gx3, sx2))));
        sy2 = fmaf(gy0, gy0, fmaf(gy1, gy1, fmaf(gy2, gy2, fmaf(gy3, gy3, sy2))));
    }
    __shared__ double sbuf[8];
    double v4[4] = {(double)sx, (double)sy, (double)sx2, (double)sy2};
#pragma unroll
    for (int qq = 0; qq < 4; ++qq) {
        double t = v4[qq];
#pragma unroll
        for (int o = 16; o; o >>= 1) t += __shfl_down_sync(0xffffffffu, t, o);
        if ((threadIdx.x & 31) == 0) sbuf[threadIdx.x >> 5] = t;
        __syncthreads();
        if (threadIdx.x < 8) {
            t = sbuf[threadIdx.x];
#pragma unroll
            for (int o = 4; o; o >>= 1) t += __shfl_down_sync(0xffu, t, o);
            if (threadIdx.x == 0) atomicAdd(&g_stats[b * 4 + qq], t);
        }
        __syncthreads();
    }
}

/* coeffs[b][t] = sum_pix pu[b][pix]*Z[t][pix]; Z computed inline per chunk. */
#define KC 64
__global__ void __launch_bounds__(128) gemm_kernel() {
    __shared__ float pm_s[BATCH][KC + 4];
    __shared__ float z_s[TP][KC + 4];
    const float* pu = (const float*)g_bufA;
    int tid = threadIdx.x;
    int b0 = (tid >> 3) * 2;
    int t0 = (tid & 7) * 7;
    float acc[2][7];
#pragma unroll
    for (int a = 0; a < 2; ++a)
#pragma unroll
        for (int j = 0; j < 7; ++j) acc[a][j] = 0.0f;

    for (int k0 = blockIdx.x * KC; k0 < NPIX; k0 += gridDim.x * KC) {
        __syncthreads();
        if (tid < 64) {
            /* compute Zernike basis * mask for pixel k0+tid */
            int pix = k0 + tid;
            int c = pix >> 10;
            int r = pix & 1023;
            float xg = (float)c * (1.0f / 256.0f) - 1.0f;
            float yg = (float)r * (2.0f / 1023.0f) - 1.0f;
            float rr = xg * xg + yg * yg;
            float rho = sqrtf(rr);
            float mk = (rho <= 1.0f) ? 1.0f : 0.0f;
            float inv = 1.0f / rho;
            float c1 = xg * inv, s1 = yg * inv;
            float q1 = rho, q2 = q1 * q1;
            float q3 = q2 * q1, q4 = q2 * q2, q5 = q3 * q2, q6 = q3 * q3;
            float q7 = q4 * q3, q8 = q4 * q4, q9 = q5 * q4;
            float c2 = c1 * c1 - s1 * s1, s2 = 2.0f * s1 * c1;
            float c3 = c1 * c2 - s1 * s2, s3 = s1 * c2 + c1 * s2;
            float c4 = c1 * c3 - s1 * s3, s4 = s1 * c3 + c1 * s3;
            float c5 = c1 * c4 - s1 * s4, s5 = s1 * c4 + c1 * s4;
            float c6 = c1 * c5 - s1 * s5, s6 = s1 * c5 + c1 * s5;
            float c7 = c1 * c6 - s1 * s6, s7 = s1 * c6 + c1 * s6;
            float c8 = c1 * c7 - s1 * s7, s8 = s1 * c7 + c1 * s7;
            float c9 = c1 * c8 - s1 * s8, s9 = s1 * c8 + c1 * s8;
#define ZST(t, val) z_s[t][tid] = (val) * mk
            ZST(0, 1.0f);
            ZST(1, q1 * s1);
            ZST(2, q1 * c1);
            ZST(3, q2 * s2);
            ZST(4, 2.0f * q2 - 1.0f);
            ZST(5, q2 * c2);
            ZST(6, q3 * s3);
            float R31 = 3.0f * q3 - 2.0f * q1;
            ZST(7, R31 * s1);
            ZST(8, R31 * c1);
            ZST(9, q3 * c3);
            ZST(10, q4 * s4);
            float R42 = 4.0f * q4 - 3.0f * q2;
            ZST(11, R42 * s2);
            ZST(12, 6.0f * q4 - 6.0f * q2 + 1.0f);
            ZST(13, R42 * c2);
            ZST(14, q4 * c4);
            ZST(15, q5 * s5);
            float R53 = 5.0f * q5 - 4.0f * q3;
            ZST(16, R53 * s3);
            float R51 = 10.0f * q5 - 12.0f * q3 + 3.0f * q1;
            ZST(17, R51 * s1);
            ZST(18, R51 * c1);
            ZST(19, R53 * c3);
            ZST(20, q5 * c5);
            ZST(21, q6 * s6);
            float R64 = 6.0f * q6 - 5.0f * q4;
            ZST(22, R64 * s4);
            float R62 = 15.0f * q6 - 20.0f * q4 + 6.0f * q2;
            ZST(23, R62 * s2);
            ZST(24, 20.0f * q6 - 30.0f * q4 + 12.0f * q2 - 1.0f);
            ZST(25, R62 * c2);
            ZST(26, R64 * c4);
            ZST(27, q6 * c6);
            ZST(28, q7 * s7);
            float R75 = 7.0f * q7 - 6.0f * q5;
            ZST(29, R75 * s5);
            float R73 = 21.0f * q7 - 30.0f * q5 + 10.0f * q3;
            ZST(30, R73 * s3);
            float R71 = 35.0f * q7 - 60.0f * q5 + 30.0f * q3 - 4.0f * q1;
            ZST(31, R71 * s1);
            ZST(32, R71 * c1);
            ZST(33, R73 * c3);
            ZST(34, R75 * c5);
            ZST(35, q7 * c7);
            ZST(36, q8 * s8);
            float R86 = 8.0f * q8 - 7.0f * q6;
            ZST(37, R86 * s6);
            float R84 = 28.0f * q8 - 42.0f * q6 + 15.0f * q4;
            ZST(38, R84 * s4);
            float R82 = 56.0f * q8 - 105.0f * q6 + 60.0f * q4 - 10.0f * q2;
            ZST(39, R82 * s2);
            ZST(40, 70.0f * q8 - 140.0f * q6 + 90.0f * q4 - 20.0f * q2 + 1.0f);
            ZST(41, R82 * c2);
            ZST(42, R84 * c4);
            ZST(43, R86 * c6);
            ZST(44, q8 * c8);
            ZST(45, q9 * s9);
            float R97 = 9.0f * q9 - 8.0f * q7;
            ZST(46, R97 * s7);
            float R95 = 36.0f * q9 - 56.0f * q7 + 21.0f * q5;
            ZST(47, R95 * s5);
            float R93 = 84.0f * q9 - 168.0f * q7 + 105.0f * q5 - 20.0f * q3;
            ZST(48, R93 * s3);
            float R91 = 126.0f * q9 - 280.0f * q7 + 210.0f * q5 - 60.0f * q3 + 5.0f * q1;
            ZST(49, R91 * s1);
            ZST(50, R91 * c1);
            ZST(51, R93 * c3);
            ZST(52, R95 * c5);
            ZST(53, R97 * c7);
            ZST(54, q9 * c9);
            z_s[55][tid] = 0.0f;
#undef ZST
            unsigned bal = __ballot_sync(0xffffffffu, mk > 0.5f);
            if ((tid & 31) == 0) atomicAdd(&g_maskcnt, __popc(bal));
        } else {
            int t = tid - 64;  /* 0..63 */
#pragma unroll
            for (int row = 0; row < BATCH; ++row)
                pm_s[row][t] = pu[(size_t)row * NPIX + k0 + t];
        }
        __syncthreads();
#pragma unroll 8
        for (int kk = 0; kk < KC; kk += 4) {
            float4 a0 = *(const float4*)&pm_s[b0][kk];
            float4 a1 = *(const float4*)&pm_s[b0 + 1][kk];
#pragma unroll
            for (int j = 0; j < 7; ++j) {
                float4 zz = *(const float4*)&z_s[t0 + j][kk];
                acc[0][j] = fmaf(a0.x, zz.x, fmaf(a0.y, zz.y, fmaf(a0.z, zz.z, fmaf(a0.w, zz.w, acc[0][j]))));
                acc[1][j] = fmaf(a1.x, zz.x, fmaf(a1.y, zz.y, fmaf(a1.z, zz.z, fmaf(a1.w, zz.w, acc[1][j]))));
            }
        }
    }
#pragma unroll
    for (int j = 0; j < 7; ++j) {
        atomicAdd(&g_coeff[(b0)     * TP + t0 + j], acc[0][j]);
        atomicAdd(&g_coeff[(b0 + 1) * TP + t0 + j], acc[1][j]);
    }
}

__global__ void finalize_kernel(float* __restrict__ out) {
    int b = blockIdx.x;
    int j = threadIdx.x;
    if (j < 55) {
        out[b * 60 + j] = g_coeff[b * TP + j] / (float)g_maskcnt;
    } else if (j < 60) {
        double N = (double)NPIX;
        double sx = g_stats[b * 4 + 0], sy = g_stats[b * 4 + 1];
        double sx2 = g_stats[b * 4 + 2], sy2 = g_stats[b * 4 + 3];
        float v;
        if (j == 55)      v = (float)(sx / N);
        else if (j == 56) v = (float)(sy / N);
        else if (j == 57) v = (float)sqrt(fmax(0.0, (sx2 - sx * sx / N) / (N - 1.0)));
        else if (j == 58) v = (float)sqrt(fmax(0.0, (sy2 - sy * sy / N) / (N - 1.0)));
        else              v = __int_as_float(g_magmax[b]);
        out[b * 60 + j] = v;
    }
}

extern "C" void kernel_launch(void* const* d_in, const int* in_sizes, int n_in,
                              void* d_out, int out_size) {
    (void)in_sizes; (void)n_in; (void)out_size;
    const float* x = (const float*)d_in[0];
    float* out = (float*)d_out;

    init_kernel<<<1, 512>>>();
    row_fft_kernel<<<BATCH * H / 2, 256>>>(x);
    transpose_kernel<<<dim3(17, H / 32, BATCH), dim3(32, 8)>>>();
    col_fft_kernel<<<BATCH * WR, 256>>>();
    stats_kernel<<<dim3(128, BATCH), 256>>>();
    gemm_kernel<<<296, 128>>>();
    finalize_kernel<<<BATCH, 64>>>(out);
}

// round 4
// speedup vs baseline: 1.5890x; 1.0316x over previous
#include <cuda_runtime.h>
#include <math.h>

#define BATCH 32
#define H 1024
#define W 1024
#define WR 513
#define NPIX (WR * H)
#define TP 56

/* padded smem index: conflict-free/low-conflict for all Stockham strides */
#define PADI(e) ((e) + 5 * ((e) >> 5))
#define FFT_SM 1184   /* PADI(1023)=1178, rounded up */

__device__ float2 g_bufA[(size_t)BATCH * H * WR];
__device__ float2 g_bufB[(size_t)BATCH * WR * H];
__device__ float2 g_tw[512];
__device__ float  g_coeff[BATCH * TP];
__device__ double g_stats[BATCH * 4];
__device__ int    g_magmax[BATCH];
__device__ int    g_maskcnt;

__device__ __forceinline__ float2 cmul(float2 a, float2 b) {
    return make_float2(a.x * b.x - a.y * b.y, a.x * b.y + a.y * b.x);
}

__global__ void init_kernel() {
    int t = threadIdx.x;
    float s, c;
    sincospif(-(float)t / 512.0f, &s, &c);
    g_tw[t] = make_float2(c, s);
    for (int i = t; i < BATCH * TP; i += 512) g_coeff[i] = 0.0f;
    if (t < BATCH * 4) g_stats[t] = 0.0;
    if (t < BATCH)     g_magmax[t] = 0;
    if (t == 0)        g_maskcnt = 0;
}

struct FFTRes { float* re; float* im; };

/* 1024-pt radix-4 Stockham, 256 threads, split re/im padded smem.
   Data must be preloaded at PADI indices of (re0,im0); caller syncs before. */
__device__ __forceinline__ FFTRes fft1024_r4s(float* re0, float* im0,
                                              float* re1, float* im1, int tid) {
    float *sr = re0, *si = im0, *dr = re1, *di = im1;
#pragma unroll
    for (int s = 0; s < 5; ++s) {
        const int Ns = 1 << (2 * s);
        int jm = tid & (Ns - 1);
        float a0r = sr[PADI(tid)],       a0i = si[PADI(tid)];
        float a1r = sr[PADI(tid + 256)], a1i = si[PADI(tid + 256)];
        float a2r = sr[PADI(tid + 512)], a2i = si[PADI(tid + 512)];
        float a3r = sr[PADI(tid + 768)], a3i = si[PADI(tid + 768)];
        int i1 = jm << (8 - 2 * s);
        float2 w1 = g_tw[i1];
        float2 w2 = g_tw[2 * i1];
        float2 w3 = cmul(w1, w2);
        float b1r = a1r * w1.x - a1i * w1.y, b1i = a1r * w1.y + a1i * w1.x;
        float b2r = a2r * w2.x - a2i * w2.y, b2i = a2r * w2.y + a2i * w2.x;
        float b3r = a3r * w3.x - a3i * w3.y, b3i = a3r * w3.y + a3i * w3.x;
        float t0r = a0r + b2r, t0i = a0i + b2i;
        float t1r = a0r - b2r, t1i = a0i - b2i;
        float t2r = b1r + b3r, t2i = b1i + b3i;
        float t3r = b1r - b3r, t3i = b1i - b3i;
        int base = ((tid >> (2 * s)) << (2 * s + 2)) | jm;
        int e0 = PADI(base);
        int e1 = PADI(base + Ns);
        int e2 = PADI(base + 2 * Ns);
        int e3 = PADI(base + 3 * Ns);
        dr[e0] = t0r + t2r;  di[e0] = t0i + t2i;
        dr[e1] = t1r + t3i;  di[e1] = t1i - t3r;   /* t1 - i*t3 */
        dr[e2] = t0r - t2r;  di[e2] = t0i - t2i;
        dr[e3] = t1r - t3i;  di[e3] = t1i + t3r;   /* t1 + i*t3 */
        float* tp;
        tp = sr; sr = dr; dr = tp;
        tp = si; si = di; di = tp;
        __syncthreads();
    }
    FFTRes res; res.re = sr; res.im = si;
    return res;
}

/* Two real rows packed into one complex FFT, Hermitian unpack. */
__global__ void __launch_bounds__(256) row_fft_kernel(const float* __restrict__ x) {
    __shared__ float sm[4][FFT_SM];
    int blk = blockIdx.x;
    int tid = threadIdx.x;
    const float* rowA = x + (size_t)(2 * blk) * W;
    const float* rowB = rowA + W;
#pragma unroll
    for (int i = 0; i < 4; ++i) {
        int idx = tid + i * 256;
        sm[0][PADI(idx)] = rowA[idx];
        sm[1][PADI(idx)] = rowB[idx];
    }
    __syncthreads();
    FFTRes res = fft1024_r4s(sm[0], sm[1], sm[2], sm[3], tid);
    float2* outA = g_bufA + (size_t)(2 * blk) * WR;
    float2* outB = outA + WR;
    for (int c = tid; c < WR; c += 256) {
        int cn = (1024 - c) & 1023;
        float Zcr = res.re[PADI(c)],  Zci = res.im[PADI(c)];
        float Znr = res.re[PADI(cn)], Zni = res.im[PADI(cn)];
        float ar = 0.5f * (Zcr + Znr);
        float ai = 0.5f * (Zci - Zni);
        float dr = Zcr - Znr;
        float di = Zci + Zni;
        outA[c] = make_float2(ar, ai);
        outB[c] = make_float2(0.5f * di, -0.5f * dr);
    }
}

__global__ void transpose_kernel() {
    __shared__ float2 tile[32][33];
    int b  = blockIdx.z;
    int c0 = blockIdx.x * 32;
    int r0 = blockIdx.y * 32;
    int tx = threadIdx.x, ty = threadIdx.y;
    const float2* A = g_bufA + (size_t)b * H * WR;
    float2*       B = g_bufB + (size_t)b * WR * H;
#pragma unroll
    for (int i = ty; i < 32; i += 8) {
        int r = r0 + i, c = c0 + tx;
        if (c < WR) tile[i][tx] = A[(size_t)r * WR + c];
    }
    __syncthreads();
#pragma unroll
    for (int i = ty; i < 32; i += 8) {
        int c = c0 + i, r = r0 + tx;
        if (c < WR) B[(size_t)c * H + r] = tile[tx][i];
    }
}

__global__ void __launch_bounds__(256) col_fft_kernel() {
    __shared__ float sm[4][FFT_SM];
    __shared__ float sred[8];
    int blk = blockIdx.x;
    int tid = threadIdx.x;
    const float2* in = g_bufB + (size_t)blk * H;
#pragma unroll
    for (int i = 0; i < 4; ++i) {
        int idx = tid + i * 256;
        float2 v = in[idx];
        sm[0][PADI(idx)] = v.x;
        sm[1][PADI(idx)] = v.y;
    }
    __syncthreads();
    FFTRes res = fft1024_r4s(sm[0], sm[1], sm[2], sm[3], tid);

    float* pu = (float*)g_bufA;
    float maxm2 = 0.0f;
#pragma unroll
    for (int i = 0; i < 4; ++i) {
        int k = tid + i * 256;
        float zr = res.re[PADI(k)], zi = res.im[PADI(k)];
        float m2 = fmaf(zr, zr, zi * zi);
        maxm2 = fmaxf(maxm2, m2);
        float ph = atan2f(zi, zr);
        if (ph < 0.0f) ph += 6.28318530717958647692f;
        pu[(size_t)blk * H + k] = ph;
    }
#pragma unroll
    for (int o = 16; o; o >>= 1) maxm2 = fmaxf(maxm2, __shfl_xor_sync(0xffffffffu, maxm2, o));
    if ((tid & 31) == 0) sred[tid >> 5] = maxm2;
    __syncthreads();
    if (tid < 8) {
        maxm2 = sred[tid];
#pragma unroll
        for (int o = 4; o; o >>= 1) maxm2 = fmaxf(maxm2, __shfl_xor_sync(0xffu, maxm2, o));
        if (tid == 0)
            atomicMax(&g_magmax[blk / WR], __float_as_int(sqrtf(maxm2)));
    }
}

__global__ void __launch_bounds__(256) stats_kernel() {
    int b = blockIdx.y;
    const float*  pu  = (const float*)g_bufA + (size_t)b * NPIX;
    const float4* pu4 = (const float4*)pu;
    float sx = 0.0f, sy = 0.0f, sx2 = 0.0f, sy2 = 0.0f;
    const int NQ = NPIX / 4;
    for (int q = blockIdx.x * 256 + threadIdx.x; q < NQ; q += gridDim.x * 256) {
        int p = q * 4;
        int r = p & 1023;
        int c = p >> 10;
        float4 v = pu4[q];
        float left  = (r == 0)        ? 0.0f : pu[p - 1];
        float right = (r + 4 == 1024) ? 0.0f : pu[p + 4];
        float gy0 = (r == 0)        ? (v.y - v.x) : 0.5f * (v.y - left);
        float gy1 = 0.5f * (v.z - v.x);
        float gy2 = 0.5f * (v.w - v.y);
        float gy3 = (r + 4 == 1024) ? (v.w - v.z) : 0.5f * (right - v.z);
        float4 up = (c == 0)      ? v : pu4[q - 256];
        float4 dn = (c == WR - 1) ? v : pu4[q + 256];
        float f = (c == 0 || c == WR - 1) ? 1.0f : 0.5f;
        float gx0 = f * (dn.x - up.x);
        float gx1 = f * (dn.y - up.y);
        float gx2 = f * (dn.z - up.z);
        float gx3 = f * (dn.w - up.w);
        sx += gx0 + gx1 + gx2 + gx3;
        sy += gy0 + gy1 + gy2 + gy3;
        sx2 = fmaf(gx0, gx0, fmaf(gx1, gx1, fmaf(gx2, gx2, fmaf(gx3, gx3, sx2))));
        sy2 = fmaf(gy0, gy0, fmaf(gy1, gy1, fmaf(gy2, gy2, fmaf(gy3, gy3, sy2))));
    }
    __shared__ double sbuf[8];
    double v4[4] = {(double)sx, (double)sy, (double)sx2, (double)sy2};
#pragma unroll
    for (int qq = 0; qq < 4; ++qq) {
        double t = v4[qq];
#pragma unroll
        for (int o = 16; o; o >>= 1) t += __shfl_down_sync(0xffffffffu, t, o);
        if ((threadIdx.x & 31) == 0) sbuf[threadIdx.x >> 5] = t;
        __syncthreads();
        if (threadIdx.x < 8) {
            t = sbuf[threadIdx.x];
#pragma unroll
            for (int o = 4; o; o >>= 1) t += __shfl_down_sync(0xffu, t, o);
            if (threadIdx.x == 0) atomicAdd(&g_stats[b * 4 + qq], t);
        }
        __syncthreads();
    }
}

#define KC 64
__global__ void __launch_bounds__(128) gemm_kernel() {
    __shared__ float pm_s[BATCH][KC + 4];
    __shared__ float z_s[TP][KC + 4];
    const float* pu = (const float*)g_bufA;
    int tid = threadIdx.x;
    int b0 = (tid >> 3) * 2;
    int t0 = (tid & 7) * 7;
    float acc[2][7];
#pragma unroll
    for (int a = 0; a < 2; ++a)
#pragma unroll
        for (int j = 0; j < 7; ++j) acc[a][j] = 0.0f;

    for (int k0 = blockIdx.x * KC; k0 < NPIX; k0 += gridDim.x * KC) {
        __syncthreads();
        if (tid < 64) {
            int pix = k0 + tid;
            int c = pix >> 10;
            int r = pix & 1023;
            float xg = (float)c * (1.0f / 256.0f) - 1.0f;
            float yg = (float)r * (2.0f / 1023.0f) - 1.0f;
            float rr = xg * xg + yg * yg;
            float rho = sqrtf(rr);
            float mk = (rho <= 1.0f) ? 1.0f : 0.0f;
            float inv = 1.0f / rho;
            float c1 = xg * inv, s1 = yg * inv;
            float q1 = rho, q2 = q1 * q1;
            float q3 = q2 * q1, q4 = q2 * q2, q5 = q3 * q2, q6 = q3 * q3;
            float q7 = q4 * q3, q8 = q4 * q4, q9 = q5 * q4;
            float c2 = c1 * c1 - s1 * s1, s2 = 2.0f * s1 * c1;
            float c3 = c1 * c2 - s1 * s2, s3 = s1 * c2 + c1 * s2;
            float c4 = c1 * c3 - s1 * s3, s4 = s1 * c3 + c1 * s3;
            float c5 = c1 * c4 - s1 * s4, s5 = s1 * c4 + c1 * s4;
            float c6 = c1 * c5 - s1 * s5, s6 = s1 * c5 + c1 * s5;
            float c7 = c1 * c6 - s1 * s6, s7 = s1 * c6 + c1 * s6;
            float c8 = c1 * c7 - s1 * s7, s8 = s1 * c7 + c1 * s7;
            float c9 = c1 * c8 - s1 * s8, s9 = s1 * c8 + c1 * s8;
#define ZST(t, val) z_s[t][tid] = (val) * mk
            ZST(0, 1.0f);
            ZST(1, q1 * s1);
            ZST(2, q1 * c1);
            ZST(3, q2 * s2);
            ZST(4, 2.0f * q2 - 1.0f);
            ZST(5, q2 * c2);
            ZST(6, q3 * s3);
            float R31 = 3.0f * q3 - 2.0f * q1;
            ZST(7, R31 * s1);
            ZST(8, R31 * c1);
            ZST(9, q3 * c3);
            ZST(10, q4 * s4);
            float R42 = 4.0f * q4 - 3.0f * q2;
            ZST(11, R42 * s2);
            ZST(12, 6.0f * q4 - 6.0f * q2 + 1.0f);
            ZST(13, R42 * c2);
            ZST(14, q4 * c4);
            ZST(15, q5 * s5);
            float R53 = 5.0f * q5 - 4.0f * q3;
            ZST(16, R53 * s3);
            float R51 = 10.0f * q5 - 12.0f * q3 + 3.0f * q1;
            ZST(17, R51 * s1);
            ZST(18, R51 * c1);
            ZST(19, R53 * c3);
            ZST(20, q5 * c5);
            ZST(21, q6 * s6);
            float R64 = 6.0f * q6 - 5.0f * q4;
            ZST(22, R64 * s4);
            float R62 = 15.0f * q6 - 20.0f * q4 + 6.0f * q2;
            ZST(23, R62 * s2);
            ZST(24, 20.0f * q6 - 30.0f * q4 + 12.0f * q2 - 1.0f);
            ZST(25, R62 * c2);
            ZST(26, R64 * c4);
            ZST(27, q6 * c6);
            ZST(28, q7 * s7);
            float R75 = 7.0f * q7 - 6.0f * q5;
            ZST(29, R75 * s5);
            float R73 = 21.0f * q7 - 30.0f * q5 + 10.0f * q3;
            ZST(30, R73 * s3);
            float R71 = 35.0f * q7 - 60.0f * q5 + 30.0f * q3 - 4.0f * q1;
            ZST(31, R71 * s1);
            ZST(32, R71 * c1);
            ZST(33, R73 * c3);
            ZST(34, R75 * c5);
            ZST(35, q7 * c7);
            ZST(36, q8 * s8);
            float R86 = 8.0f * q8 - 7.0f * q6;
            ZST(37, R86 * s6);
            float R84 = 28.0f * q8 - 42.0f * q6 + 15.0f * q4;
            ZST(38, R84 * s4);
            float R82 = 56.0f * q8 - 105.0f * q6 + 60.0f * q4 - 10.0f * q2;
            ZST(39, R82 * s2);
            ZST(40, 70.0f * q8 - 140.0f * q6 + 90.0f * q4 - 20.0f * q2 + 1.0f);
            ZST(41, R82 * c2);
            ZST(42, R84 * c4);
            ZST(43, R86 * c6);
            ZST(44, q8 * c8);
            ZST(45, q9 * s9);
            float R97 = 9.0f * q9 - 8.0f * q7;
            ZST(46, R97 * s7);
            float R95 = 36.0f * q9 - 56.0f * q7 + 21.0f * q5;
            ZST(47, R95 * s5);
            float R93 = 84.0f * q9 - 168.0f * q7 + 105.0f * q5 - 20.0f * q3;
            ZST(48, R93 * s3);
            float R91 = 126.0f * q9 - 280.0f * q7 + 210.0f * q5 - 60.0f * q3 + 5.0f * q1;
            ZST(49, R91 * s1);
            ZST(50, R91 * c1);
            ZST(51, R93 * c3);
            ZST(52, R95 * c5);
            ZST(53, R97 * c7);
            ZST(54, q9 * c9);
            z_s[55][tid] = 0.0f;
#undef ZST
            unsigned bal = __ballot_sync(0xffffffffu, mk > 0.5f);
            if ((tid & 31) == 0) atomicAdd(&g_maskcnt, __popc(bal));
        } else {
            int t = tid - 64;
#pragma unroll
            for (int row = 0; row < BATCH; ++row)
                pm_s[row][t] = pu[(size_t)row * NPIX + k0 + t];
        }
        __syncthreads();
#pragma unroll 8
        for (int kk = 0; kk < KC; kk += 4) {
            float4 a0 = *(const float4*)&pm_s[b0][kk];
            float4 a1 = *(const float4*)&pm_s[b0 + 1][kk];
#pragma unroll
            for (int j = 0; j < 7; ++j) {
                float4 zz = *(const float4*)&z_s[t0 + j][kk];
                acc[0][j] = fmaf(a0.x, zz.x, fmaf(a0.y, zz.y, fmaf(a0.z, zz.z, fmaf(a0.w, zz.w, acc[0][j]))));
                acc[1][j] = fmaf(a1.x, zz.x, fmaf(a1.y, zz.y, fmaf(a1.z, zz.z, fmaf(a1.w, zz.w, acc[1][j]))));
            }
        }
    }
#pragma unroll
    for (int j = 0; j < 7; ++j) {
        atomicAdd(&g_coeff[(b0)     * TP + t0 + j], acc[0][j]);
        atomicAdd(&g_coeff[(b0 + 1) * TP + t0 + j], acc[1][j]);
    }
}

__global__ void finalize_kernel(float* __restrict__ out) {
    int b = blockIdx.x;
    int j = threadIdx.x;
    if (j < 55) {
        out[b * 60 + j] = g_coeff[b * TP + j] / (float)g_maskcnt;
    } else if (j < 60) {
        double N = (double)NPIX;
        double sx = g_stats[b * 4 + 0], sy = g_stats[b * 4 + 1];
        double sx2 = g_stats[b * 4 + 2], sy2 = g_stats[b * 4 + 3];
        float v;
        if (j == 55)      v = (float)(sx / N);
        else if (j == 56) v = (float)(sy / N);
        else if (j == 57) v = (float)sqrt(fmax(0.0, (sx2 - sx * sx / N) / (N - 1.0)));
        else if (j == 58) v = (float)sqrt(fmax(0.0, (sy2 - sy * sy / N) / (N - 1.0)));
        else              v = __int_as_float(g_magmax[b]);
        out[b * 60 + j] = v;
    }
}

extern "C" void kernel_launch(void* const* d_in, const int* in_sizes, int n_in,
                              void* d_out, int out_size) {
    (void)in_sizes; (void)n_in; (void)out_size;
    const float* x = (const float*)d_in[0];
    float* out = (float*)d_out;

    init_kernel<<<1, 512>>>();
    row_fft_kernel<<<BATCH * H / 2, 256>>>(x);
    transpose_kernel<<<dim3(17, H / 32, BATCH), dim3(32, 8)>>>();
    col_fft_kernel<<<BATCH * WR, 256>>>();
    stats_kernel<<<dim3(128, BATCH), 256>>>();
    gemm_kernel<<<592, 128>>>();
    finalize_kernel<<<BATCH, 64>>>(out);
}

// round 5
// speedup vs baseline: 1.9713x; 1.2406x over previous
#include <cuda_runtime.h>
#include <math.h>

#define BATCH 32
#define H 1024
#define W 1024
#define WR 513
#define NPIX (WR * H)
#define TP 56
#define TWO_PI 6.28318530717958647692f

#define PADI(e) ((e) + 5 * ((e) >> 5))
#define FFT_SM 1184

__device__ float2 g_bufA[(size_t)BATCH * H * WR];
__device__ float2 g_bufB[(size_t)BATCH * WR * H];
__device__ float2 g_tw[1024];
__device__ float  g_coeff[BATCH * TP];
__device__ double g_stats[BATCH * 4];
__device__ int    g_magmax[BATCH];
__device__ int    g_maskcnt;

__global__ void init_kernel() {
    int t = threadIdx.x;   /* 1024 threads */
    float s, c;
    sincospif(-(float)t / 512.0f, &s, &c);   /* exp(-2*pi*i*t/1024) */
    g_tw[t] = make_float2(c, s);
    if (t < BATCH * TP) g_coeff[t] = 0.0f;
    if (t >= 1024 - BATCH * TP && t - (1024 - BATCH * TP) < BATCH * TP)
        g_coeff[t - (1024 - BATCH * TP)] = 0.0f;  /* covered anyway; keep simple */
    if (t < BATCH * 4) g_stats[t] = 0.0;
    if (t < BATCH)     g_magmax[t] = 0;
    if (t == 0)        g_maskcnt = 0;
}

/* DFT-16 fully in registers. v[m] -> V[p]; m=a+4b, p=c+4d:
   V[c+4d] = DFT4_a( W16^{ac} * DFT4_b(v[a+4b])[c] )[d]          */
__device__ __forceinline__ void dft16(float* vr, float* vi) {
    const float C1 = 0.92387953251128675613f;  /* cos(pi/8)  */
    const float S1 = 0.38268343236508977173f;  /* sin(pi/8)  */
    const float C2 = 0.70710678118654752440f;
    /* W16^k = (cos, -sin)(2*pi*k/16); needed k: 1,2,3,4,6,9 */
    float tr[4][4], ti[4][4];
#pragma unroll
    for (int a = 0; a < 4; ++a) {
        float x0r = vr[a],      x0i = vi[a];
        float x1r = vr[a + 4],  x1i = vi[a + 4];
        float x2r = vr[a + 8],  x2i = vi[a + 8];
        float x3r = vr[a + 12], x3i = vi[a + 12];
        float s0r = x0r + x2r, s0i = x0i + x2i;
        float d0r = x0r - x2r, d0i = x0i - x2i;
        float s1r = x1r + x3r, s1i = x1i + x3i;
        float d1r = x1r - x3r, d1i = x1i - x3i;
        tr[a][0] = s0r + s1r; ti[a][0] = s0i + s1i;
        tr[a][1] = d0r + d1i; ti[a][1] = d0i - d1r;
        tr[a][2] = s0r - s1r; ti[a][2] = s0i - s1i;
        tr[a][3] = d0r - d1i; ti[a][3] = d0i + d1r;
    }
    /* twiddle W16^{ac} */
#pragma unroll
    for (int a = 1; a < 4; ++a) {
#pragma unroll
        for (int c = 1; c < 4; ++c) {
            int k = a * c;  /* 1,2,3,2,4,6,3,6,9 */
            float wr, wi;
            if (k == 1)      { wr =  C1; wi = -S1; }
            else if (k == 2) { wr =  C2; wi = -C2; }
            else if (k == 3) { wr =  S1; wi = -C1; }
            else if (k == 4) { wr = 0.f; wi = -1.f; }
            else if (k == 6) { wr = -C2; wi = -C2; }
            else             { wr = -C1; wi =  S1; }  /* k==9 */
            float r = tr[a][c] * wr - ti[a][c] * wi;
            ti[a][c] = tr[a][c] * wi + ti[a][c] * wr;
            tr[a][c] = r;
        }
    }
    /* DFT4 over a, output V[c+4d] */
#pragma unroll
    for (int c = 0; c < 4; ++c) {
        float s0r = tr[0][c] + tr[2][c], s0i = ti[0][c] + ti[2][c];
        float d0r = tr[0][c] - tr[2][c], d0i = ti[0][c] - ti[2][c];
        float s1r = tr[1][c] + tr[3][c], s1i = ti[1][c] + ti[3][c];
        float d1r = tr[1][c] - tr[3][c], d1i = ti[1][c] - ti[3][c];
        vr[c]      = s0r + s1r; vi[c]      = s0i + s1i;
        vr[c + 4]  = d0r + d1i; vi[c + 4]  = d0i - d1r;
        vr[c + 8]  = s0r - s1r; vi[c + 8]  = s0i - s1i;
        vr[c + 12] = d0r - d1i; vi[c + 12] = d0i + d1r;
    }
}

/* stages 0..1 shared by both FFT kernels: input already in vr/vi (stage0 src),
   on return stage-1 results are in SR/SI (padded), synced. */
__device__ __forceinline__ void fft_stages01(float* vr, float* vi,
                                             float* SR, float* SI, int t) {
    dft16(vr, vi);  /* stage0, Ns=1, no twiddles */
#pragma unroll
    for (int k = 0; k < 16; ++k) {
        int e = PADI(16 * t + k);
        SR[e] = vr[k]; SI[e] = vi[k];
    }
    __syncthreads();
    /* stage1: R=16, Ns=16 */
#pragma unroll
    for (int m = 0; m < 16; ++m) {
        int e = PADI(t + 64 * m);
        vr[m] = SR[e]; vi[m] = SI[e];
    }
    int jm = t & 15;
#pragma unroll
    for (int m = 1; m < 16; ++m) {
        float2 w = g_tw[4 * m * jm];
        float r = vr[m] * w.x - vi[m] * w.y;
        vi[m] = vr[m] * w.y + vi[m] * w.x;
        vr[m] = r;
    }
    dft16(vr, vi);
    __syncthreads();   /* all reads done before in-place writes */
    int base1 = (t >> 4) * 256 + jm;
#pragma unroll
    for (int k = 0; k < 16; ++k) {
        int e = PADI(base1 + 16 * k);
        SR[e] = vr[k]; SI[e] = vi[k];
    }
    __syncthreads();
}

/* stage2 radix-4 butterfly for group u; returns y in yr/yi, out index j+256k */
__device__ __forceinline__ void fft_stage2(const float* SR, const float* SI,
                                           int j, float* yr, float* yi) {
    float ar[4], ai[4];
#pragma unroll
    for (int m = 0; m < 4; ++m) {
        int e = PADI(j + 256 * m);
        ar[m] = SR[e]; ai[m] = SI[e];
    }
#pragma unroll
    for (int m = 1; m < 4; ++m) {
        float2 w = g_tw[m * j];
        float r = ar[m] * w.x - ai[m] * w.y;
        ai[m] = ar[m] * w.y + ai[m] * w.x;
        ar[m] = r;
    }
    float s0r = ar[0] + ar[2], s0i = ai[0] + ai[2];
    float d0r = ar[0] - ar[2], d0i = ai[0] - ai[2];
    float s1r = ar[1] + ar[3], s1i = ai[1] + ai[3];
    float d1r = ar[1] - ar[3], d1i = ai[1] - ai[3];
    yr[0] = s0r + s1r; yi[0] = s0i + s1i;
    yr[1] = d0r + d1i; yi[1] = d0i - d1r;
    yr[2] = s0r - s1r; yi[2] = s0i - s1i;
    yr[3] = d0r - d1i; yi[3] = d0i + d1r;
}

/* Two real rows packed per FFT; 2 FFTs per block. */
__global__ void __launch_bounds__(128) row_fft_kernel(const float* __restrict__ x) {
    __shared__ float smr[2][FFT_SM], smi[2][FFT_SM];
    int f = threadIdx.x >> 6;
    int t = threadIdx.x & 63;
    int pr = blockIdx.x * 2 + f;           /* row-pair index */
    float* SR = smr[f]; float* SI = smi[f];
    const float* rowA = x + (size_t)(2 * pr) * W;
    const float* rowB = rowA + W;
    float vr[16], vi[16];
#pragma unroll
    for (int m = 0; m < 16; ++m) {
        int idx = t + 64 * m;
        vr[m] = rowA[idx]; vi[m] = rowB[idx];
    }
    fft_stages01(vr, vi, SR, SI, t);
    /* stage2: write back into same smem (per-thread index set is closed) */
#pragma unroll
    for (int u = 0; u < 4; ++u) {
        int j = t + 64 * u;
        float yr[4], yi[4];
        fft_stage2(SR, SI, j, yr, yi);
#pragma unroll
        for (int k = 0; k < 4; ++k) {
            int e = PADI(j + 256 * k);
            SR[e] = yr[k]; SI[e] = yi[k];
        }
    }
    __syncthreads();
    /* Hermitian unpack */
    float2* outA = g_bufA + (size_t)(2 * pr) * WR;
    float2* outB = outA + WR;
    for (int c = t; c < WR; c += 64) {
        int cn = (1024 - c) & 1023;
        float Zcr = SR[PADI(c)],  Zci = SI[PADI(c)];
        float Znr = SR[PADI(cn)], Zni = SI[PADI(cn)];
        float ar = 0.5f * (Zcr + Znr);
        float ai = 0.5f * (Zci - Zni);
        float dr = Zcr - Znr;
        float di = Zci + Zni;
        outA[c] = make_float2(ar, ai);
        outB[c] = make_float2(0.5f * di, -0.5f * dr);
    }
}

__global__ void transpose_kernel() {
    __shared__ float2 tile[32][33];
    int b  = blockIdx.z;
    int c0 = blockIdx.x * 32;
    int r0 = blockIdx.y * 32;
    int tx = threadIdx.x, ty = threadIdx.y;
    const float2* A = g_bufA + (size_t)b * H * WR;
    float2*       B = g_bufB + (size_t)b * WR * H;
#pragma unroll
    for (int i = ty; i < 32; i += 8) {
        int r = r0 + i, c = c0 + tx;
        if (c < WR) tile[i][tx] = A[(size_t)r * WR + c];
    }
    __syncthreads();
#pragma unroll
    for (int i = ty; i < 32; i += 8) {
        int c = c0 + i, r = r0 + tx;
        if (c < WR) B[(size_t)c * H + r] = tile[tx][i];
    }
}

__global__ void __launch_bounds__(128) col_fft_kernel() {
    __shared__ float smr[2][FFT_SM], smi[2][FFT_SM];
    __shared__ float sred[4];
    int f = threadIdx.x >> 6;
    int t = threadIdx.x & 63;
    int blk = blockIdx.x * 2 + f;          /* b*WR + c */
    float* SR = smr[f]; float* SI = smi[f];
    const float2* in = g_bufB + (size_t)blk * H;
    float vr[16], vi[16];
#pragma unroll
    for (int m = 0; m < 16; ++m) {
        float2 z = in[t + 64 * m];
        vr[m] = z.x; vi[m] = z.y;
    }
    fft_stages01(vr, vi, SR, SI, t);

    float* pu = (float*)g_bufA;
    size_t outb = (size_t)blk * H;
    float maxm2 = 0.0f;
#pragma unroll
    for (int u = 0; u < 4; ++u) {
        int j = t + 64 * u;
        float yr[4], yi[4];
        fft_stage2(SR, SI, j, yr, yi);
#pragma unroll
        for (int k = 0; k < 4; ++k) {
            float m2 = fmaf(yr[k], yr[k], yi[k] * yi[k]);
            maxm2 = fmaxf(maxm2, m2);
            float ph = atan2f(yi[k], yr[k]);
            if (ph < 0.0f) ph += TWO_PI;
            pu[outb + j + 256 * k] = ph;
        }
    }
#pragma unroll
    for (int o = 16; o; o >>= 1) maxm2 = fmaxf(maxm2, __shfl_xor_sync(0xffffffffu, maxm2, o));
    int wid = threadIdx.x >> 5;            /* 0..3; warps 2f, 2f+1 belong to FFT f */
    if ((threadIdx.x & 31) == 0) sred[wid] = maxm2;
    __syncthreads();
    if (t == 0) {
        float mm = fmaxf(sred[2 * f], sred[2 * f + 1]);
        atomicMax(&g_magmax[blk / WR], __float_as_int(sqrtf(mm)));
    }
}

__global__ void __launch_bounds__(256) stats_kernel() {
    int b = blockIdx.y;
    const float*  pu  = (const float*)g_bufA + (size_t)b * NPIX;
    const float4* pu4 = (const float4*)pu;
    float sx = 0.0f, sy = 0.0f, sx2 = 0.0f, sy2 = 0.0f;
    const int NQ = NPIX / 4;
    for (int q = blockIdx.x * 256 + threadIdx.x; q < NQ; q += gridDim.x * 256) {
        int p = q * 4;
        int r = p & 1023;
        int c = p >> 10;
        float4 v = pu4[q];
        float left  = (r == 0)        ? 0.0f : pu[p - 1];
        float right = (r + 4 == 1024) ? 0.0f : pu[p + 4];
        float gy0 = (r == 0)        ? (v.y - v.x) : 0.5f * (v.y - left);
        float gy1 = 0.5f * (v.z - v.x);
        float gy2 = 0.5f * (v.w - v.y);
        float gy3 = (r + 4 == 1024) ? (v.w - v.z) : 0.5f * (right - v.z);
        float4 up = (c == 0)      ? v : pu4[q - 256];
        float4 dn = (c == WR - 1) ? v : pu4[q + 256];
        float fac = (c == 0 || c == WR - 1) ? 1.0f : 0.5f;
        float gx0 = fac * (dn.x - up.x);
        float gx1 = fac * (dn.y - up.y);
        float gx2 = fac * (dn.z - up.z);
        float gx3 = fac * (dn.w - up.w);
        sx += gx0 + gx1 + gx2 + gx3;
        sy += gy0 + gy1 + gy2 + gy3;
        sx2 = fmaf(gx0, gx0, fmaf(gx1, gx1, fmaf(gx2, gx2, fmaf(gx3, gx3, sx2))));
        sy2 = fmaf(gy0, gy0, fmaf(gy1, gy1, fmaf(gy2, gy2, fmaf(gy3, gy3, sy2))));
    }
    __shared__ double sbuf[8];
    double v4[4] = {(double)sx, (double)sy, (double)sx2, (double)sy2};
#pragma unroll
    for (int qq = 0; qq < 4; ++qq) {
        double tt = v4[qq];
#pragma unroll
        for (int o = 16; o; o >>= 1) tt += __shfl_down_sync(0xffffffffu, tt, o);
        if ((threadIdx.x & 31) == 0) sbuf[threadIdx.x >> 5] = tt;
        __syncthreads();
        if (threadIdx.x < 8) {
            tt = sbuf[threadIdx.x];
#pragma unroll
            for (int o = 4; o; o >>= 1) tt += __shfl_down_sync(0xffu, tt, o);
            if (threadIdx.x == 0) atomicAdd(&g_stats[b * 4 + qq], tt);
        }
        __syncthreads();
    }
}

#define KC 64
__global__ void __launch_bounds__(128) gemm_kernel() {
    __shared__ float pm_s[BATCH][KC + 4];
    __shared__ float z_s[TP][KC + 4];
    const float* pu = (const float*)g_bufA;
    int tid = threadIdx.x;
    int b0 = (tid >> 3) * 2;
    int t0 = (tid & 7) * 7;
    float acc[2][7];
#pragma unroll
    for (int a = 0; a < 2; ++a)
#pragma unroll
        for (int j = 0; j < 7; ++j) acc[a][j] = 0.0f;

    for (int k0 = blockIdx.x * KC; k0 < NPIX; k0 += gridDim.x * KC) {
        __syncthreads();
        if (tid < 64) {
            int pix = k0 + tid;
            int c = pix >> 10;
            int r = pix & 1023;
            float xg = (float)c * (1.0f / 256.0f) - 1.0f;
            float yg = (float)r * (2.0f / 1023.0f) - 1.0f;
            float rr = xg * xg + yg * yg;
            float rho = sqrtf(rr);
            float mk = (rho <= 1.0f) ? 1.0f : 0.0f;
            float inv = 1.0f / rho;
            float c1 = xg * inv, s1 = yg * inv;
            float q1 = rho, q2 = q1 * q1;
            float q3 = q2 * q1, q4 = q2 * q2, q5 = q3 * q2, q6 = q3 * q3;
            float q7 = q4 * q3, q8 = q4 * q4, q9 = q5 * q4;
            float c2 = c1 * c1 - s1 * s1, s2 = 2.0f * s1 * c1;
            float c3 = c1 * c2 - s1 * s2, s3 = s1 * c2 + c1 * s2;
            float c4 = c1 * c3 - s1 * s3, s4 = s1 * c3 + c1 * s3;
            float c5 = c1 * c4 - s1 * s4, s5 = s1 * c4 + c1 * s4;
            float c6 = c1 * c5 - s1 * s5, s6 = s1 * c5 + c1 * s5;
            float c7 = c1 * c6 - s1 * s6, s7 = s1 * c6 + c1 * s6;
            float c8 = c1 * c7 - s1 * s7, s8 = s1 * c7 + c1 * s7;
            float c9 = c1 * c8 - s1 * s8, s9 = s1 * c8 + c1 * s8;
#define ZST(t, val) z_s[t][tid] = (val) * mk
            ZST(0, 1.0f);
            ZST(1, q1 * s1);
            ZST(2, q1 * c1);
            ZST(3, q2 * s2);
            ZST(4, 2.0f * q2 - 1.0f);
            ZST(5, q2 * c2);
            ZST(6, q3 * s3);
            float R31 = 3.0f * q3 - 2.0f * q1;
            ZST(7, R31 * s1);
            ZST(8, R31 * c1);
            ZST(9, q3 * c3);
            ZST(10, q4 * s4);
            float R42 = 4.0f * q4 - 3.0f * q2;
            ZST(11, R42 * s2);
            ZST(12, 6.0f * q4 - 6.0f * q2 + 1.0f);
            ZST(13, R42 * c2);
            ZST(14, q4 * c4);
            ZST(15, q5 * s5);
            float R53 = 5.0f * q5 - 4.0f * q3;
            ZST(16, R53 * s3);
            float R51 = 10.0f * q5 - 12.0f * q3 + 3.0f * q1;
            ZST(17, R51 * s1);
            ZST(18, R51 * c1);
            ZST(19, R53 * c3);
            ZST(20, q5 * c5);
            ZST(21, q6 * s6);
            float R64 = 6.0f * q6 - 5.0f * q4;
            ZST(22, R64 * s4);
            float R62 = 15.0f * q6 - 20.0f * q4 + 6.0f * q2;
            ZST(23, R62 * s2);
            ZST(24, 20.0f * q6 - 30.0f * q4 + 12.0f * q2 - 1.0f);
            ZST(25, R62 * c2);
            ZST(26, R64 * c4);
            ZST(27, q6 * c6);
            ZST(28, q7 * s7);
            float R75 = 7.0f * q7 - 6.0f * q5;
            ZST(29, R75 * s5);
            float R73 = 21.0f * q7 - 30.0f * q5 + 10.0f * q3;
            ZST(30, R73 * s3);
            float R71 = 35.0f * q7 - 60.0f * q5 + 30.0f * q3 - 4.0f * q1;
            ZST(31, R71 * s1);
            ZST(32, R71 * c1);
            ZST(33, R73 * c3);
            ZST(34, R75 * c5);
            ZST(35, q7 * c7);
            ZST(36, q8 * s8);
            float R86 = 8.0f * q8 - 7.0f * q6;
            ZST(37, R86 * s6);
            float R84 = 28.0f * q8 - 42.0f * q6 + 15.0f * q4;
            ZST(38, R84 * s4);
            float R82 = 56.0f * q8 - 105.0f * q6 + 60.0f * q4 - 10.0f * q2;
            ZST(39, R82 * s2);
            ZST(40, 70.0f * q8 - 140.0f * q6 + 90.0f * q4 - 20.0f * q2 + 1.0f);
            ZST(41, R82 * c2);
            ZST(42, R84 * c4);
            ZST(43, R86 * c6);
            ZST(44, q8 * c8);
            ZST(45, q9 * s9);
            float R97 = 9.0f * q9 - 8.0f * q7;
            ZST(46, R97 * s7);
            float R95 = 36.0f * q9 - 56.0f * q7 + 21.0f * q5;
            ZST(47, R95 * s5);
            float R93 = 84.0f * q9 - 168.0f * q7 + 105.0f * q5 - 20.0f * q3;
            ZST(48, R93 * s3);
            float R91 = 126.0f * q9 - 280.0f * q7 + 210.0f * q5 - 60.0f * q3 + 5.0f * q1;
            ZST(49, R91 * s1);
            ZST(50, R91 * c1);
            ZST(51, R93 * c3);
            ZST(52, R95 * c5);
            ZST(53, R97 * c7);
            ZST(54, q9 * c9);
            z_s[55][tid] = 0.0f;
#undef ZST
            unsigned bal = __ballot_sync(0xffffffffu, mk > 0.5f);
            if ((tid & 31) == 0) atomicAdd(&g_maskcnt, __popc(bal));
        } else {
            int t = tid - 64;
#pragma unroll
            for (int row = 0; row < BATCH; ++row)
                pm_s[row][t] = pu[(size_t)row * NPIX + k0 + t];
        }
        __syncthreads();
#pragma unroll 8
        for (int kk = 0; kk < KC; kk += 4) {
            float4 a0 = *(const float4*)&pm_s[b0][kk];
            float4 a1 = *(const float4*)&pm_s[b0 + 1][kk];
#pragma unroll
            for (int j = 0; j < 7; ++j) {
                float4 zz = *(const float4*)&z_s[t0 + j][kk];
                acc[0][j] = fmaf(a0.x, zz.x, fmaf(a0.y, zz.y, fmaf(a0.z, zz.z, fmaf(a0.w, zz.w, acc[0][j]))));
                acc[1][j] = fmaf(a1.x, zz.x, fmaf(a1.y, zz.y, fmaf(a1.z, zz.z, fmaf(a1.w, zz.w, acc[1][j]))));
            }
        }
    }
#pragma unroll
    for (int j = 0; j < 7; ++j) {
        atomicAdd(&g_coeff[(b0)     * TP + t0 + j], acc[0][j]);
        atomicAdd(&g_coeff[(b0 + 1) * TP + t0 + j], acc[1][j]);
    }
}

__global__ void finalize_kernel(float* __restrict__ out) {
    int b = blockIdx.x;
    int j = threadIdx.x;
    if (j < 55) {
        out[b * 60 + j] = g_coeff[b * TP + j] / (float)g_maskcnt;
    } else if (j < 60) {
        double N = (double)NPIX;
        double sx = g_stats[b * 4 + 0], sy = g_stats[b * 4 + 1];
        double sx2 = g_stats[b * 4 + 2], sy2 = g_stats[b * 4 + 3];
        float v;
        if (j == 55)      v = (float)(sx / N);
        else if (j == 56) v = (float)(sy / N);
        else if (j == 57) v = (float)sqrt(fmax(0.0, (sx2 - sx * sx / N) / (N - 1.0)));
        else if (j == 58) v = (float)sqrt(fmax(0.0, (sy2 - sy * sy / N) / (N - 1.0)));
        else              v = __int_as_float(g_magmax[b]);
        out[b * 60 + j] = v;
    }
}

extern "C" void kernel_launch(void* const* d_in, const int* in_sizes, int n_in,
                              void* d_out, int out_size) {
    (void)in_sizes; (void)n_in; (void)out_size;
    const float* x = (const float*)d_in[0];
    float* out = (float*)d_out;

    init_kernel<<<1, 1024>>>();
    row_fft_kernel<<<BATCH * H / 4, 128>>>(x);      /* 8192 blocks, 2 FFTs each */
    transpose_kernel<<<dim3(17, H / 32, BATCH), dim3(32, 8)>>>();
    col_fft_kernel<<<BATCH * WR / 2, 128>>>();      /* 8208 blocks */
    stats_kernel<<<dim3(128, BATCH), 256>>>();
    gemm_kernel<<<592, 128>>>();
    finalize_kernel<<<BATCH, 64>>>(out);
}